// round 8
// baseline (speedup 1.0000x reference)
#include <cuda_runtime.h>
#include <cstdint>
#include <cstddef>

// ---------------------------------------------------------------------------
// BiLSTM T=1024 B=32 H=256 L=3, 3-gate cell, highway on l>0.
//   zx GEMMs: FFMA2 SGEMM, duplicated-B smem (no packs in inner loop).
//   recurrence: 16 clusters x 8 CTAs (dir x 4-batch group). Wh in registers;
//   h exchanged as DUPLICATED f32x2 via DSMEM (consumer needs no packs);
//   single count-8 mbarrier per CTA, parallel release-arrives (threads 0-7).
// ---------------------------------------------------------------------------

#define T_LEN 1024
#define BATCH 32
#define ZN    768
#define MROWS (T_LEN*BATCH)

__device__ float g_zxf[(size_t)MROWS * ZN];
__device__ float g_zxb[(size_t)MROWS * ZN];
__device__ float g_buf0[(size_t)MROWS * 512];
__device__ float g_buf1[(size_t)MROWS * 512];

__device__ __forceinline__ float sigm(float x) { return 1.f / (1.f + __expf(-x)); }

__device__ __forceinline__ unsigned long long pack2(float lo, float hi) {
    unsigned long long r;
    asm("mov.b64 %0, {%1, %2};" : "=l"(r) : "f"(lo), "f"(hi));
    return r;
}
__device__ __forceinline__ void unpack2(unsigned long long v, float& lo, float& hi) {
    asm("mov.b64 {%0, %1}, %2;" : "=f"(lo), "=f"(hi) : "l"(v));
}
__device__ __forceinline__ void ffma2(unsigned long long& d, unsigned long long a, unsigned long long b) {
    asm("fma.rn.f32x2 %0, %1, %2, %3;" : "=l"(d) : "l"(a), "l"(b), "l"(d));
}
__device__ __forceinline__ unsigned smaddr(const void* p) {
    unsigned a;
    asm("{ .reg .u64 t; cvta.to.shared.u64 t, %1; cvt.u32.u64 %0, t; }" : "=r"(a) : "l"(p));
    return a;
}
__device__ __forceinline__ unsigned mapa_addr(unsigned addr, unsigned rank) {
    unsigned ra;
    asm("mapa.shared::cluster.u32 %0, %1, %2;" : "=r"(ra) : "r"(addr), "r"(rank));
    return ra;
}
__device__ __forceinline__ void st_dsmem_u64x2(unsigned raddr, unsigned long long a, unsigned long long b) {
    asm volatile("st.shared::cluster.v2.u64 [%0], {%1,%2};"
                 :: "r"(raddr), "l"(a), "l"(b) : "memory");
}
__device__ __forceinline__ void mbar_init(unsigned addr, unsigned cnt) {
    asm volatile("mbarrier.init.shared.b64 [%0], %1;" :: "r"(addr), "r"(cnt) : "memory");
}
__device__ __forceinline__ void mbar_arrive_dsmem(unsigned raddr) {
    asm volatile("mbarrier.arrive.shared::cluster.b64 _, [%0];" :: "r"(raddr) : "memory");
}
__device__ __forceinline__ void fence_cluster() {
    asm volatile("fence.acq_rel.cluster;" ::: "memory");
}
__device__ __forceinline__ void mbar_wait(unsigned addr, unsigned parity) {
    unsigned done;
    asm volatile("{ .reg .pred p; "
                 "mbarrier.try_wait.parity.acquire.cta.shared::cta.b64 p, [%1], %2; "
                 "selp.b32 %0, 1, 0, p; }"
                 : "=r"(done) : "r"(addr), "r"(parity) : "memory");
    if (!done) {
        asm volatile("{ .reg .pred P1; "
                     "WL_%=: mbarrier.try_wait.parity.acquire.cta.shared::cta.b64 P1, [%0], %1, 0x989680; "
                     "@P1 bra.uni WD_%=; bra.uni WL_%=; WD_%=: }"
                     :: "r"(addr), "r"(parity) : "memory");
    }
}
#define CLUSTER_SYNC() do { \
    asm volatile("barrier.cluster.arrive.aligned;" ::: "memory"); \
    asm volatile("barrier.cluster.wait.aligned;" ::: "memory"); \
} while (0)

// ------------------------- SGEMM (FFMA2, duplicated-B smem) ----------------
#define BM 128
#define BN 64
#define BK 16

__global__ __launch_bounds__(256) void sgemm_bias(
    const float* __restrict__ A, const float* __restrict__ B,
    const float* __restrict__ bias, float* __restrict__ C,
    int M, int N, int K)
{
    __shared__ float As[2][BK][BM];                      // 16 KB
    __shared__ unsigned long long Bsd[2][BK][BN];        // duplicated, 16 KB

    const int bm = blockIdx.y * BM;
    const int bn = blockIdx.x * BN;
    const int tid = threadIdx.x;
    const int tx = tid & 15;
    const int ty = tid >> 4;

    const int ar0 = tid >> 2;
    const int ac4 = tid & 3;
    const int brow = tid >> 4;
    const int bc4 = tid & 15;

    unsigned long long acc2[4][4];
#pragma unroll
    for (int p = 0; p < 4; p++)
#pragma unroll
        for (int j = 0; j < 4; j++) acc2[p][j] = 0ull;

    const int nIter = K >> 4;

    float4 a0, a1, b0;
    a0 = *(const float4*)(A + (size_t)(bm + ar0) * K + ac4 * 4);
    a1 = *(const float4*)(A + (size_t)(bm + 64 + ar0) * K + ac4 * 4);
    b0 = *(const float4*)(B + (size_t)brow * N + bn + bc4 * 4);

    for (int it = 0; it < nIter; it++) {
        const int s = it & 1;
        As[s][ac4 * 4 + 0][ar0] = a0.x;
        As[s][ac4 * 4 + 1][ar0] = a0.y;
        As[s][ac4 * 4 + 2][ar0] = a0.z;
        As[s][ac4 * 4 + 3][ar0] = a0.w;
        As[s][ac4 * 4 + 0][64 + ar0] = a1.x;
        As[s][ac4 * 4 + 1][64 + ar0] = a1.y;
        As[s][ac4 * 4 + 2][64 + ar0] = a1.z;
        As[s][ac4 * 4 + 3][64 + ar0] = a1.w;
        Bsd[s][brow][bc4 * 4 + 0] = pack2(b0.x, b0.x);
        Bsd[s][brow][bc4 * 4 + 1] = pack2(b0.y, b0.y);
        Bsd[s][brow][bc4 * 4 + 2] = pack2(b0.z, b0.z);
        Bsd[s][brow][bc4 * 4 + 3] = pack2(b0.w, b0.w);
        __syncthreads();
        if (it + 1 < nIter) {
            int k0 = (it + 1) * BK;
            a0 = *(const float4*)(A + (size_t)(bm + ar0) * K + k0 + ac4 * 4);
            a1 = *(const float4*)(A + (size_t)(bm + 64 + ar0) * K + k0 + ac4 * 4);
            b0 = *(const float4*)(B + (size_t)(k0 + brow) * N + bn + bc4 * 4);
        }
#pragma unroll
        for (int k = 0; k < BK; k++) {
            ulonglong2 A0 = *(const ulonglong2*)&As[s][k][ty * 8];
            ulonglong2 A1 = *(const ulonglong2*)&As[s][k][ty * 8 + 4];
            ulonglong2 B01 = *(const ulonglong2*)&Bsd[s][k][tx * 4];
            ulonglong2 B23 = *(const ulonglong2*)&Bsd[s][k][tx * 4 + 2];
            ffma2(acc2[0][0], A0.x, B01.x); ffma2(acc2[1][0], A0.y, B01.x);
            ffma2(acc2[2][0], A1.x, B01.x); ffma2(acc2[3][0], A1.y, B01.x);
            ffma2(acc2[0][1], A0.x, B01.y); ffma2(acc2[1][1], A0.y, B01.y);
            ffma2(acc2[2][1], A1.x, B01.y); ffma2(acc2[3][1], A1.y, B01.y);
            ffma2(acc2[0][2], A0.x, B23.x); ffma2(acc2[1][2], A0.y, B23.x);
            ffma2(acc2[2][2], A1.x, B23.x); ffma2(acc2[3][2], A1.y, B23.x);
            ffma2(acc2[0][3], A0.x, B23.y); ffma2(acc2[1][3], A0.y, B23.y);
            ffma2(acc2[2][3], A1.x, B23.y); ffma2(acc2[3][3], A1.y, B23.y);
        }
        __syncthreads();
    }
    float4 bb = *(const float4*)(bias + bn + tx * 4);
#pragma unroll
    for (int p = 0; p < 4; p++) {
        float lo[4], hi[4];
#pragma unroll
        for (int j = 0; j < 4; j++) unpack2(acc2[p][j], lo[j], hi[j]);
        int row0 = bm + ty * 8 + 2 * p;
        float4 o0, o1;
        o0.x = lo[0] + bb.x; o0.y = lo[1] + bb.y; o0.z = lo[2] + bb.z; o0.w = lo[3] + bb.w;
        o1.x = hi[0] + bb.x; o1.y = hi[1] + bb.y; o1.z = hi[2] + bb.z; o1.w = hi[3] + bb.w;
        *(float4*)(C + (size_t)row0 * N + bn + tx * 4)       = o0;
        *(float4*)(C + (size_t)(row0 + 1) * N + bn + tx * 4) = o1;
    }
}

// ------------------------- recurrent scan ----------------------------------
// 128 CTAs, cluster 8. cid = blockIdx.x/8; dir = cid>>3; bg = cid&7.
// CTA rank r owns h-cols [r*32, r*32+32) -> 96 z-cols x 4 batches. 384 thr.
// h exchanged DUPLICATED: HSd[buf][b*264 + k] is f32x2 (both halves = h).
// Dot: (jg = tid%24, kc = tid/24), W in regs (32 ull), zero packs.
// Partials ZP[b][kc][j] (pitch 104/kc, 1672/b). Reduce on all 384 threads.
// Cell warps: math -> duplicated push (16 lanes/warp ST.128) -> bar(128) ->
// threads 0-7 fence+release-arrive all ranks' count-8 mbar -> THEN y store.
#define ZP_KP 104
#define ZP_BP 1672

__global__ void __cluster_dims__(8, 1, 1) __launch_bounds__(384, 1)
recur8(const float* __restrict__ Whf, const float* __restrict__ Whb,
       const float* __restrict__ h0, const float* __restrict__ c0,
       float* __restrict__ y, float* __restrict__ hn, float* __restrict__ cn,
       int layer)
{
    __shared__ unsigned long long HSd[2][4 * 264];   // duplicated h, 16.9 KB
    __shared__ float ZP[4 * ZP_BP];                  // dot partials
    __shared__ float ZF[96 * 4];                     // reduced gate sums
    __shared__ unsigned long long SHd[4 * 40];       // duplicated nh staging
    __shared__ unsigned long long hmb;               // count-8 mbarrier

    const int cid = blockIdx.x >> 3;
    const int dir = cid >> 3;
    const int bg  = cid & 7;
    unsigned rank;
    asm("mov.u32 %0, %%cluster_ctarank;" : "=r"(rank));

    const float* Wh = dir ? Whb : Whf;
    const float* zx = dir ? g_zxb : g_zxf;
    const int tid = threadIdx.x;
    const unsigned hmb_a = smaddr(&hmb);

    const int jg = tid % 24;
    const int kc = tid / 24;
    const int rj = tid >> 2;
    const int rb = tid & 3;
    const int bglob_r = bg * 4 + rb;
    const int zcolr = (rj >> 5) * 256 + (int)rank * 32 + (rj & 31);

    // ---- DSMEM rank deltas ----
    const unsigned anchor = smaddr(&HSd[0][0]);
    unsigned pdelta[8];
#pragma unroll
    for (int r = 0; r < 8; r++) pdelta[r] = mapa_addr(anchor, (unsigned)r) - anchor;

    // ---- W slice into registers ----
    const int gate = jg >> 3;
    const int colb = (int)rank * 32 + (jg & 7) * 4;
    const int zc0 = gate * 256 + colb;
    unsigned long long wA[16], wB[16];
#pragma unroll
    for (int kl = 0; kl < 16; kl++) {
        const float* wrow = Wh + (size_t)(kc * 16 + kl) * ZN + zc0;
        wA[kl] = pack2(__ldg(wrow + 0), __ldg(wrow + 1));
        wB[kl] = pack2(__ldg(wrow + 2), __ldg(wrow + 3));
    }

    // ---- init duplicated h buffer 0, c, mbarrier ----
    for (int it = tid; it < 4 * 256; it += 384) {
        int b = it >> 8, k = it & 255;
        float v = h0[k];
        HSd[0][b * 264 + k] = pack2(v, v);
    }
    float creg = 0.f;
    if (tid < 128) creg = c0[(int)rank * 32 + (tid >> 2)];
    if (tid == 0) mbar_init(hmb_a, 8);
    __syncthreads();
    CLUSTER_SYNC();   // inits + HSd[0] visible cluster-wide

    const int t0 = dir ? (T_LEN - 1) : 0;
    float zxv = __ldg(&zx[((size_t)t0 * BATCH + bglob_r) * ZN + zcolr]);

    for (int tt = 0; tt < T_LEN; tt++) {
        const int t = dir ? (T_LEN - 1 - tt) : tt;

        if (tt) mbar_wait(hmb_a, (tt & 1) ^ 1);   // h[tt&1] ready

        // ---------------- dot (W regs x duplicated-h smem, no packs) ------
        const unsigned long long* hc = &HSd[tt & 1][kc * 16];
        unsigned long long acc[2][4];
#pragma unroll
        for (int g2 = 0; g2 < 2; g2++)
#pragma unroll
            for (int b = 0; b < 4; b++) acc[g2][b] = 0ull;

#pragma unroll
        for (int q = 0; q < 4; q++) {
#define RQ(B)                                                              \
            {                                                              \
                ulonglong2 hA = *(const ulonglong2*)(hc + B * 264 + q * 4);    \
                ulonglong2 hB = *(const ulonglong2*)(hc + B * 264 + q * 4 + 2);\
                ffma2(acc[0][B], wA[q * 4 + 0], hA.x);                     \
                ffma2(acc[1][B], wB[q * 4 + 0], hA.x);                     \
                ffma2(acc[0][B], wA[q * 4 + 1], hA.y);                     \
                ffma2(acc[1][B], wB[q * 4 + 1], hA.y);                     \
                ffma2(acc[0][B], wA[q * 4 + 2], hB.x);                     \
                ffma2(acc[1][B], wB[q * 4 + 2], hB.x);                     \
                ffma2(acc[0][B], wA[q * 4 + 3], hB.y);                     \
                ffma2(acc[1][B], wB[q * 4 + 3], hB.y);                     \
            }
            RQ(0) RQ(1) RQ(2) RQ(3)
#undef RQ
        }
#pragma unroll
        for (int b = 0; b < 4; b++) {
            ulonglong2 v;
            v.x = acc[0][b];
            v.y = acc[1][b];
            *(ulonglong2*)&ZP[b * ZP_BP + kc * ZP_KP + jg * 4] = v;
        }
        __syncthreads();   // bar 1: ZP ready

        // ---------------- reduce: all 384 threads, one (j,b) each ---------
        {
            float s = zxv;
            const float* zp = &ZP[rb * ZP_BP + rj];
#pragma unroll
            for (int k2 = 0; k2 < 16; k2++) s += zp[k2 * ZP_KP];
            ZF[rj * 4 + rb] = s;
        }
        if (tt + 1 < T_LEN) {
            const int tn = dir ? (t - 1) : (t + 1);
            zxv = __ldg(&zx[((size_t)tn * BATCH + bglob_r) * ZN + zcolr]);
        }
        __syncthreads();   // bar 2: ZF ready

        // ---------------- cell + duplicated push + arrives + y ------------
        if (tid < 128) {
            const int m = tid >> 2;
            const int b = tid & 3;
            const int w = tid >> 5;
            const int lane = tid & 31;
            float iv = ZF[m * 4 + b];
            float jv = ZF[(32 + m) * 4 + b];
            float ov = ZF[(64 + m) * 4 + b];
            float ig = sigm(iv);
            creg = (1.f - ig) * creg + ig * tanhf(jv);
            float nh = tanhf(creg) * sigm(ov);

            SHd[b * 40 + m] = pack2(nh, nh);
            __syncwarp();
            if ((tt + 1 < T_LEN) && lane < 16) {
                const int pb = lane & 3, cp = lane >> 2;          // col-pair
                const int base = w * 8 + cp * 2;
                ulonglong2 v = *(const ulonglong2*)&SHd[pb * 40 + base];
                unsigned la = smaddr(&HSd[(tt + 1) & 1][pb * 264 + (int)rank * 32 + base]);
#pragma unroll
                for (int r2 = 0; r2 < 8; r2++) st_dsmem_u64x2(la + pdelta[r2], v.x, v.y);
            }
            asm volatile("bar.sync 1, 128;" ::: "memory");   // all pushes issued
            if ((tt + 1 < T_LEN) && tid < 8) {
                fence_cluster();
                mbar_arrive_dsmem(hmb_a + pdelta[tid]);      // my slot, peer tid
            }

            // off the critical chain: output writes after the arrive
            const int col = (int)rank * 32 + m;
            const int bglob = bg * 4 + b;
            y[((size_t)t * BATCH + bglob) * 512 + dir * 256 + col] = nh;
            if (tt == T_LEN - 1) {
                int si = 2 * layer + dir;
                hn[(size_t)si * (BATCH * 256) + bglob * 256 + col] = nh;
                cn[(size_t)si * (BATCH * 256) + bglob * 256 + col] = creg;
            }
        }
        // non-cell warps proceed straight to next step's mbar wait
    }
}

// ------------------------- highway elementwise -----------------------------
__global__ __launch_bounds__(256) void highway_ew(
    const float4* __restrict__ gz, const float4* __restrict__ raw,
    const float4* __restrict__ prev, float4* __restrict__ dst, int n4)
{
    int i = blockIdx.x * blockDim.x + threadIdx.x;
    if (i < n4) {
        float4 G = gz[i], R = raw[i], P = prev[i], o;
        float s;
        s = sigm(G.x); o.x = s * R.x + (1.f - s) * P.x;
        s = sigm(G.y); o.y = s * R.y + (1.f - s) * P.y;
        s = sigm(G.z); o.z = s * R.z + (1.f - s) * P.z;
        s = sigm(G.w); o.w = s * R.w + (1.f - s) * P.w;
        dst[i] = o;
    }
}

// ------------------------- host launcher -----------------------------------
extern "C" void kernel_launch(void* const* d_in, const int* in_sizes, int n_in,
                              void* d_out, int out_size)
{
    (void)in_sizes; (void)n_in; (void)out_size;

    const float* x    = (const float*)d_in[0];
    const float* h0   = (const float*)d_in[1];
    const float* c0   = (const float*)d_in[2];
    const float* Wf0  = (const float*)d_in[3];
    const float* bf0  = (const float*)d_in[4];
    const float* Wb0  = (const float*)d_in[5];
    const float* bb0  = (const float*)d_in[6];
    const float* Wf1  = (const float*)d_in[7];
    const float* bf1  = (const float*)d_in[8];
    const float* Wb1  = (const float*)d_in[9];
    const float* bb1  = (const float*)d_in[10];
    const float* Wf2  = (const float*)d_in[11];
    const float* bf2  = (const float*)d_in[12];
    const float* Wb2  = (const float*)d_in[13];
    const float* bb2  = (const float*)d_in[14];
    const float* W_hw = (const float*)d_in[15];
    const float* b_hw = (const float*)d_in[16];

    float* out = (float*)d_out;
    float* hn  = out + (size_t)MROWS * 512;
    float* cn  = hn + 6 * BATCH * 256;

    float *zxf, *zxb, *buf0, *buf1;
    cudaGetSymbolAddress((void**)&zxf,  g_zxf);
    cudaGetSymbolAddress((void**)&zxb,  g_zxb);
    cudaGetSymbolAddress((void**)&buf0, g_buf0);
    cudaGetSymbolAddress((void**)&buf1, g_buf1);

    const dim3 g768(ZN / BN, MROWS / BM);
    const dim3 g512(512 / BN, MROWS / BM);
    const int n4 = (MROWS * 512) / 4;
    const int ewb = (n4 + 255) / 256;

    // ---- layer 0 ----
    sgemm_bias<<<g768, 256>>>(x, Wf0, bf0, zxf, MROWS, ZN, 256);
    sgemm_bias<<<g768, 256>>>(x, Wb0, bb0, zxb, MROWS, ZN, 256);
    recur8<<<128, 384>>>(Wf0 + (size_t)256 * ZN, Wb0 + (size_t)256 * ZN,
                         h0, c0, buf0, hn, cn, 0);
    // ---- layer 1 ----
    sgemm_bias<<<g768, 256>>>(buf0, Wf1, bf1, zxf, MROWS, ZN, 512);
    sgemm_bias<<<g768, 256>>>(buf0, Wb1, bb1, zxb, MROWS, ZN, 512);
    recur8<<<128, 384>>>(Wf1 + (size_t)512 * ZN, Wb1 + (size_t)512 * ZN,
                         h0, c0, buf1, hn, cn, 1);
    sgemm_bias<<<g512, 256>>>(buf1, W_hw, b_hw, zxf, MROWS, 512, 512);
    highway_ew<<<ewb, 256>>>((const float4*)zxf, (const float4*)buf1,
                             (const float4*)buf0, (float4*)buf1, n4);
    // ---- layer 2 ----
    sgemm_bias<<<g768, 256>>>(buf1, Wf2, bf2, zxf, MROWS, ZN, 512);
    sgemm_bias<<<g768, 256>>>(buf1, Wb2, bb2, zxb, MROWS, ZN, 512);
    recur8<<<128, 384>>>(Wf2 + (size_t)512 * ZN, Wb2 + (size_t)512 * ZN,
                         h0, c0, buf0, hn, cn, 2);
    sgemm_bias<<<g512, 256>>>(buf0, W_hw, b_hw, zxf, MROWS, 512, 512);
    highway_ew<<<ewb, 256>>>((const float4*)zxf, (const float4*)buf0,
                             (const float4*)buf1, (float4*)out, n4);
}

// round 9
// speedup vs baseline: 1.2957x; 1.2957x over previous
#include <cuda_runtime.h>
#include <cstdint>
#include <cstddef>

// ---------------------------------------------------------------------------
// BiLSTM T=1024 B=32 H=256 L=3, 3-gate cell, highway on l>0.
//   zx GEMMs: FFMA2 SGEMM, 2-stage double-buffered pipeline (R5-proven).
//   recurrence: 16 clusters x 8 CTAs (dir x 4-batch group). Wh in registers;
//   h exchanged via vectorized DSMEM stores; count-8 mbarrier per CTA.
//   R9: fast tanh (expf-based), outputs off the critical chain, zx in reg.
// ---------------------------------------------------------------------------

#define T_LEN 1024
#define BATCH 32
#define ZN    768
#define MROWS (T_LEN*BATCH)

__device__ float g_zxf[(size_t)MROWS * ZN];
__device__ float g_zxb[(size_t)MROWS * ZN];
__device__ float g_buf0[(size_t)MROWS * 512];
__device__ float g_buf1[(size_t)MROWS * 512];

__device__ __forceinline__ float sigm(float x) { return 1.f / (1.f + __expf(-x)); }
// tanh via fast exp: (1-e^{-2x})/(1+e^{-2x}); clamp keeps exp finite.
__device__ __forceinline__ float tanh_fast(float x) {
    float xc = fminf(fmaxf(x, -15.f), 15.f);
    float t = __expf(-2.f * xc);
    return __fdividef(1.f - t, 1.f + t);
}

__device__ __forceinline__ unsigned long long pack2(float lo, float hi) {
    unsigned long long r;
    asm("mov.b64 %0, {%1, %2};" : "=l"(r) : "f"(lo), "f"(hi));
    return r;
}
__device__ __forceinline__ void unpack2(unsigned long long v, float& lo, float& hi) {
    asm("mov.b64 {%0, %1}, %2;" : "=f"(lo), "=f"(hi) : "l"(v));
}
__device__ __forceinline__ void ffma2(unsigned long long& d, unsigned long long a, unsigned long long b) {
    asm("fma.rn.f32x2 %0, %1, %2, %3;" : "=l"(d) : "l"(a), "l"(b), "l"(d));
}
__device__ __forceinline__ unsigned smaddr(const void* p) {
    unsigned a;
    asm("{ .reg .u64 t; cvta.to.shared.u64 t, %1; cvt.u32.u64 %0, t; }" : "=r"(a) : "l"(p));
    return a;
}
__device__ __forceinline__ void st_cluster_f128(unsigned addr, unsigned rank, float4 v) {
    asm volatile("{ .reg .b32 ra; mapa.shared::cluster.u32 ra, %0, %1; "
                 "st.shared::cluster.v4.f32 [ra], {%2,%3,%4,%5}; }"
                 :: "r"(addr), "r"(rank), "f"(v.x), "f"(v.y), "f"(v.z), "f"(v.w) : "memory");
}
__device__ __forceinline__ void mbar_init(unsigned addr, unsigned cnt) {
    asm volatile("mbarrier.init.shared.b64 [%0], %1;" :: "r"(addr), "r"(cnt) : "memory");
}
__device__ __forceinline__ void mbar_arrive_remote(unsigned addr, unsigned rank) {
    asm volatile("{ .reg .b32 ra; mapa.shared::cluster.u32 ra, %0, %1; "
                 "mbarrier.arrive.shared::cluster.b64 _, [ra]; }"
                 :: "r"(addr), "r"(rank) : "memory");
}
__device__ __forceinline__ void fence_cluster() {
    asm volatile("fence.acq_rel.cluster;" ::: "memory");
}
__device__ __forceinline__ void mbar_wait(unsigned addr, unsigned parity) {
    unsigned done;
    asm volatile("{ .reg .pred p; "
                 "mbarrier.try_wait.parity.acquire.cta.shared::cta.b64 p, [%1], %2; "
                 "selp.b32 %0, 1, 0, p; }"
                 : "=r"(done) : "r"(addr), "r"(parity) : "memory");
    if (!done) {
        asm volatile("{ .reg .pred P1; "
                     "WL_%=: mbarrier.try_wait.parity.acquire.cta.shared::cta.b64 P1, [%0], %1, 0x989680; "
                     "@P1 bra.uni WD_%=; bra.uni WL_%=; WD_%=: }"
                     :: "r"(addr), "r"(parity) : "memory");
    }
}
#define CLUSTER_SYNC() do { \
    asm volatile("barrier.cluster.arrive.aligned;" ::: "memory"); \
    asm volatile("barrier.cluster.wait.aligned;" ::: "memory"); \
} while (0)

// ------------------------- SGEMM (FFMA2, 2-stage pipeline) -----------------
#define BM 128
#define BN 64
#define BK 16

__global__ __launch_bounds__(256) void sgemm_bias(
    const float* __restrict__ A, const float* __restrict__ B,
    const float* __restrict__ bias, float* __restrict__ C,
    int M, int N, int K)
{
    __shared__ float As[2][BK][BM];
    __shared__ float Bs[2][BK][BN];

    const int bm = blockIdx.y * BM;
    const int bn = blockIdx.x * BN;
    const int tid = threadIdx.x;
    const int tx = tid & 15;
    const int ty = tid >> 4;

    const int ar0 = tid >> 2;
    const int ac4 = tid & 3;
    const int brow = tid >> 4;
    const int bc4 = tid & 15;

    unsigned long long acc2[4][4];
#pragma unroll
    for (int p = 0; p < 4; p++)
#pragma unroll
        for (int j = 0; j < 4; j++) acc2[p][j] = 0ull;

    const int nIter = K >> 4;

    float4 a0, a1, b0;
    a0 = *(const float4*)(A + (size_t)(bm + ar0) * K + ac4 * 4);
    a1 = *(const float4*)(A + (size_t)(bm + 64 + ar0) * K + ac4 * 4);
    b0 = *(const float4*)(B + (size_t)brow * N + bn + bc4 * 4);

    for (int it = 0; it < nIter; it++) {
        const int s = it & 1;
        As[s][ac4 * 4 + 0][ar0] = a0.x;
        As[s][ac4 * 4 + 1][ar0] = a0.y;
        As[s][ac4 * 4 + 2][ar0] = a0.z;
        As[s][ac4 * 4 + 3][ar0] = a0.w;
        As[s][ac4 * 4 + 0][64 + ar0] = a1.x;
        As[s][ac4 * 4 + 1][64 + ar0] = a1.y;
        As[s][ac4 * 4 + 2][64 + ar0] = a1.z;
        As[s][ac4 * 4 + 3][64 + ar0] = a1.w;
        *(float4*)&Bs[s][brow][bc4 * 4] = b0;
        __syncthreads();
        if (it + 1 < nIter) {
            int k0 = (it + 1) * BK;
            a0 = *(const float4*)(A + (size_t)(bm + ar0) * K + k0 + ac4 * 4);
            a1 = *(const float4*)(A + (size_t)(bm + 64 + ar0) * K + k0 + ac4 * 4);
            b0 = *(const float4*)(B + (size_t)(k0 + brow) * N + bn + bc4 * 4);
        }
#pragma unroll
        for (int k = 0; k < BK; k++) {
            ulonglong2 A0 = *(const ulonglong2*)&As[s][k][ty * 8];
            ulonglong2 A1 = *(const ulonglong2*)&As[s][k][ty * 8 + 4];
            float4 bv = *(const float4*)&Bs[s][k][tx * 4];
            unsigned long long bb0 = pack2(bv.x, bv.x);
            unsigned long long bb1 = pack2(bv.y, bv.y);
            unsigned long long bb2 = pack2(bv.z, bv.z);
            unsigned long long bb3 = pack2(bv.w, bv.w);
            ffma2(acc2[0][0], A0.x, bb0); ffma2(acc2[1][0], A0.y, bb0);
            ffma2(acc2[2][0], A1.x, bb0); ffma2(acc2[3][0], A1.y, bb0);
            ffma2(acc2[0][1], A0.x, bb1); ffma2(acc2[1][1], A0.y, bb1);
            ffma2(acc2[2][1], A1.x, bb1); ffma2(acc2[3][1], A1.y, bb1);
            ffma2(acc2[0][2], A0.x, bb2); ffma2(acc2[1][2], A0.y, bb2);
            ffma2(acc2[2][2], A1.x, bb2); ffma2(acc2[3][2], A1.y, bb2);
            ffma2(acc2[0][3], A0.x, bb3); ffma2(acc2[1][3], A0.y, bb3);
            ffma2(acc2[2][3], A1.x, bb3); ffma2(acc2[3][3], A1.y, bb3);
        }
        __syncthreads();
    }
    float4 bb = *(const float4*)(bias + bn + tx * 4);
#pragma unroll
    for (int p = 0; p < 4; p++) {
        float lo[4], hi[4];
#pragma unroll
        for (int j = 0; j < 4; j++) unpack2(acc2[p][j], lo[j], hi[j]);
        int row0 = bm + ty * 8 + 2 * p;
        float4 o0, o1;
        o0.x = lo[0] + bb.x; o0.y = lo[1] + bb.y; o0.z = lo[2] + bb.z; o0.w = lo[3] + bb.w;
        o1.x = hi[0] + bb.x; o1.y = hi[1] + bb.y; o1.z = hi[2] + bb.z; o1.w = hi[3] + bb.w;
        *(float4*)(C + (size_t)row0 * N + bn + tx * 4)       = o0;
        *(float4*)(C + (size_t)(row0 + 1) * N + bn + tx * 4) = o1;
    }
}

// ------------------------- recurrent scan ----------------------------------
// 128 CTAs, cluster 8. cid = blockIdx.x/8; dir = cid>>3; bg = cid&7.
// CTA rank r owns h-cols [r*32, r*32+32) -> 96 z-cols x 4 batches. 384 thr.
// Dot: (jg = tid%24, kc = tid/24), W in regs (32 ull).
// Partials ZP[b][kc][j] (pitch 104/kc, 1672/b). Reduce on all 384 threads
// (zx carried in register). Cell: fast tanh; h pushed via
// st.shared::cluster.v4 (8 lanes/warp); count-8 mbarrier, tid0 arrives;
// y/hn/cn stores AFTER the arrive (off the inter-CTA critical chain).
#define ZP_KP 104
#define ZP_BP 1672

__global__ void __cluster_dims__(8, 1, 1) __launch_bounds__(384, 1)
recur9(const float* __restrict__ Whf, const float* __restrict__ Whb,
       const float* __restrict__ h0, const float* __restrict__ c0,
       float* __restrict__ y, float* __restrict__ hn, float* __restrict__ cn,
       int layer)
{
    __shared__ float HS[2][4 * 264];     // h pingpong, [b][k] pitch 264
    __shared__ float ZP[4 * ZP_BP];      // dot partials
    __shared__ float ZF[96 * 4];         // reduced gate sums
    __shared__ float SH[4 * 40];         // nh staging for vector pushes
    __shared__ unsigned long long hmb;   // arrival mbarrier (count 8)

    const int cid = blockIdx.x >> 3;
    const int dir = cid >> 3;
    const int bg  = cid & 7;
    unsigned rank;
    asm("mov.u32 %0, %%cluster_ctarank;" : "=r"(rank));

    const float* Wh = dir ? Whb : Whf;
    const float* zx = dir ? g_zxb : g_zxf;
    const int tid = threadIdx.x;
    const unsigned hmb_a = smaddr(&hmb);

    const int jg = tid % 24;
    const int kc = tid / 24;
    const int rj = tid >> 2;
    const int rb = tid & 3;
    const int bglob_r = bg * 4 + rb;
    const int zcolr = (rj >> 5) * 256 + (int)rank * 32 + (rj & 31);

    // ---- W slice into registers ----
    const int gate = jg >> 3;
    const int colb = (int)rank * 32 + (jg & 7) * 4;
    const int zc0 = gate * 256 + colb;
    unsigned long long wA[16], wB[16];
#pragma unroll
    for (int kl = 0; kl < 16; kl++) {
        const float* wrow = Wh + (size_t)(kc * 16 + kl) * ZN + zc0;
        wA[kl] = pack2(__ldg(wrow + 0), __ldg(wrow + 1));
        wB[kl] = pack2(__ldg(wrow + 2), __ldg(wrow + 3));
    }

    // ---- init h buffer 0, c, mbarrier ----
    for (int it = tid; it < 4 * 256; it += 384) {
        int b = it >> 8, k = it & 255;
        HS[0][b * 264 + k] = h0[k];
    }
    float creg = 0.f;
    if (tid < 128) creg = c0[(int)rank * 32 + (tid >> 2)];
    if (tid == 0) mbar_init(hmb_a, 8);
    __syncthreads();
    CLUSTER_SYNC();   // inits + HS[0] visible cluster-wide before any arrive

    const int t0 = dir ? (T_LEN - 1) : 0;
    float zxv = __ldg(&zx[((size_t)t0 * BATCH + bglob_r) * ZN + zcolr]);

    for (int tt = 0; tt < T_LEN; tt++) {
        const int t = dir ? (T_LEN - 1 - tt) : tt;

        if (tt) mbar_wait(hmb_a, (tt & 1) ^ 1);   // h[tt&1] ready

        // ---------------- dot (W in regs, h broadcast from SMEM) ----------
        const float* hc = &HS[tt & 1][kc * 16];
        unsigned long long acc[2][4];
#pragma unroll
        for (int g2 = 0; g2 < 2; g2++)
#pragma unroll
            for (int b = 0; b < 4; b++) acc[g2][b] = 0ull;

#pragma unroll
        for (int q = 0; q < 4; q++) {
            float4 h0q = *(const float4*)(hc + 0 * 264 + q * 4);
            float4 h1q = *(const float4*)(hc + 1 * 264 + q * 4);
            float4 h2q = *(const float4*)(hc + 2 * 264 + q * 4);
            float4 h3q = *(const float4*)(hc + 3 * 264 + q * 4);
#define RSTEP(C, KL)                                                   \
            {                                                          \
                unsigned long long p;                                  \
                p = pack2(h0q.C, h0q.C);                               \
                ffma2(acc[0][0], wA[KL], p); ffma2(acc[1][0], wB[KL], p); \
                p = pack2(h1q.C, h1q.C);                               \
                ffma2(acc[0][1], wA[KL], p); ffma2(acc[1][1], wB[KL], p); \
                p = pack2(h2q.C, h2q.C);                               \
                ffma2(acc[0][2], wA[KL], p); ffma2(acc[1][2], wB[KL], p); \
                p = pack2(h3q.C, h3q.C);                               \
                ffma2(acc[0][3], wA[KL], p); ffma2(acc[1][3], wB[KL], p); \
            }
            RSTEP(x, (q * 4 + 0)) RSTEP(y, (q * 4 + 1))
            RSTEP(z, (q * 4 + 2)) RSTEP(w, (q * 4 + 3))
#undef RSTEP
        }
#pragma unroll
        for (int b = 0; b < 4; b++) {
            ulonglong2 v;
            v.x = acc[0][b];
            v.y = acc[1][b];
            *(ulonglong2*)&ZP[b * ZP_BP + kc * ZP_KP + jg * 4] = v;
        }
        __syncthreads();   // bar 1: ZP ready

        // ---------------- reduce: all 384 threads, one (j,b) each ---------
        {
            float s = zxv;
            const float* zp = &ZP[rb * ZP_BP + rj];
#pragma unroll
            for (int k2 = 0; k2 < 16; k2++) s += zp[k2 * ZP_KP];
            ZF[rj * 4 + rb] = s;
        }
        if (tt + 1 < T_LEN) {   // prefetch next zx (current consumed above)
            const int tn = dir ? (t - 1) : (t + 1);
            zxv = __ldg(&zx[((size_t)tn * BATCH + bglob_r) * ZN + zcolr]);
        }
        __syncthreads();   // bar 2: ZF ready

        // ---------------- cell + vectorized h push ------------------------
        float nh = 0.f;
        if (tid < 128) {
            const int m = tid >> 2;
            const int b = tid & 3;
            const int w = tid >> 5;
            const int lane = tid & 31;
            float iv = ZF[m * 4 + b];
            float jv = ZF[(32 + m) * 4 + b];
            float ov = ZF[(64 + m) * 4 + b];
            float ig = sigm(iv);
            creg = (1.f - ig) * creg + ig * tanh_fast(jv);
            nh = tanh_fast(creg) * sigm(ov);

            SH[b * 40 + m] = nh;
            __syncwarp();
            if ((tt + 1 < T_LEN) && lane < 8) {
                const int pb = lane & 3, half = lane >> 2;
                const int base = w * 8 + half * 4;
                float4 v = *(const float4*)&SH[pb * 40 + base];
                unsigned ha = smaddr(&HS[(tt + 1) & 1][pb * 264 + (int)rank * 32 + base]);
#pragma unroll
                for (unsigned r2 = 0; r2 < 8; r2++) st_cluster_f128(ha, r2, v);
            }
        }
        if (tt + 1 < T_LEN) {
            __syncthreads();                     // all pushes issued
            if (tid == 0) {
                fence_cluster();                 // make DSMEM stores visible
#pragma unroll
                for (unsigned r2 = 0; r2 < 8; r2++) mbar_arrive_remote(hmb_a, r2);
            }
        }
        // off the inter-CTA critical chain: output writes after the arrive
        if (tid < 128) {
            const int m = tid >> 2;
            const int b = tid & 3;
            const int col = (int)rank * 32 + m;
            const int bglob = bg * 4 + b;
            y[((size_t)t * BATCH + bglob) * 512 + dir * 256 + col] = nh;
            if (tt == T_LEN - 1) {
                int si = 2 * layer + dir;
                hn[(size_t)si * (BATCH * 256) + bglob * 256 + col] = nh;
                cn[(size_t)si * (BATCH * 256) + bglob * 256 + col] = creg;
            }
        }
    }
}

// ------------------------- highway elementwise -----------------------------
__global__ __launch_bounds__(256) void highway_ew(
    const float4* __restrict__ gz, const float4* __restrict__ raw,
    const float4* __restrict__ prev, float4* __restrict__ dst, int n4)
{
    int i = blockIdx.x * blockDim.x + threadIdx.x;
    if (i < n4) {
        float4 G = gz[i], R = raw[i], P = prev[i], o;
        float s;
        s = sigm(G.x); o.x = s * R.x + (1.f - s) * P.x;
        s = sigm(G.y); o.y = s * R.y + (1.f - s) * P.y;
        s = sigm(G.z); o.z = s * R.z + (1.f - s) * P.z;
        s = sigm(G.w); o.w = s * R.w + (1.f - s) * P.w;
        dst[i] = o;
    }
}

// ------------------------- host launcher -----------------------------------
extern "C" void kernel_launch(void* const* d_in, const int* in_sizes, int n_in,
                              void* d_out, int out_size)
{
    (void)in_sizes; (void)n_in; (void)out_size;

    const float* x    = (const float*)d_in[0];
    const float* h0   = (const float*)d_in[1];
    const float* c0   = (const float*)d_in[2];
    const float* Wf0  = (const float*)d_in[3];
    const float* bf0  = (const float*)d_in[4];
    const float* Wb0  = (const float*)d_in[5];
    const float* bb0  = (const float*)d_in[6];
    const float* Wf1  = (const float*)d_in[7];
    const float* bf1  = (const float*)d_in[8];
    const float* Wb1  = (const float*)d_in[9];
    const float* bb1  = (const float*)d_in[10];
    const float* Wf2  = (const float*)d_in[11];
    const float* bf2  = (const float*)d_in[12];
    const float* Wb2  = (const float*)d_in[13];
    const float* bb2  = (const float*)d_in[14];
    const float* W_hw = (const float*)d_in[15];
    const float* b_hw = (const float*)d_in[16];

    float* out = (float*)d_out;
    float* hn  = out + (size_t)MROWS * 512;
    float* cn  = hn + 6 * BATCH * 256;

    float *zxf, *zxb, *buf0, *buf1;
    cudaGetSymbolAddress((void**)&zxf,  g_zxf);
    cudaGetSymbolAddress((void**)&zxb,  g_zxb);
    cudaGetSymbolAddress((void**)&buf0, g_buf0);
    cudaGetSymbolAddress((void**)&buf1, g_buf1);

    const dim3 g768(ZN / BN, MROWS / BM);
    const dim3 g512(512 / BN, MROWS / BM);
    const int n4 = (MROWS * 512) / 4;
    const int ewb = (n4 + 255) / 256;

    // ---- layer 0 ----
    sgemm_bias<<<g768, 256>>>(x, Wf0, bf0, zxf, MROWS, ZN, 256);
    sgemm_bias<<<g768, 256>>>(x, Wb0, bb0, zxb, MROWS, ZN, 256);
    recur9<<<128, 384>>>(Wf0 + (size_t)256 * ZN, Wb0 + (size_t)256 * ZN,
                         h0, c0, buf0, hn, cn, 0);
    // ---- layer 1 ----
    sgemm_bias<<<g768, 256>>>(buf0, Wf1, bf1, zxf, MROWS, ZN, 512);
    sgemm_bias<<<g768, 256>>>(buf0, Wb1, bb1, zxb, MROWS, ZN, 512);
    recur9<<<128, 384>>>(Wf1 + (size_t)512 * ZN, Wb1 + (size_t)512 * ZN,
                         h0, c0, buf1, hn, cn, 1);
    sgemm_bias<<<g512, 256>>>(buf1, W_hw, b_hw, zxf, MROWS, 512, 512);
    highway_ew<<<ewb, 256>>>((const float4*)zxf, (const float4*)buf1,
                             (const float4*)buf0, (float4*)buf1, n4);
    // ---- layer 2 ----
    sgemm_bias<<<g768, 256>>>(buf1, Wf2, bf2, zxf, MROWS, ZN, 512);
    sgemm_bias<<<g768, 256>>>(buf1, Wb2, bb2, zxb, MROWS, ZN, 512);
    recur9<<<128, 384>>>(Wf2 + (size_t)512 * ZN, Wb2 + (size_t)512 * ZN,
                         h0, c0, buf0, hn, cn, 2);
    sgemm_bias<<<g512, 256>>>(buf0, W_hw, b_hw, zxf, MROWS, 512, 512);
    highway_ew<<<ewb, 256>>>((const float4*)zxf, (const float4*)buf0,
                             (const float4*)buf1, (float4*)out, n4);
}

// round 10
// speedup vs baseline: 1.6755x; 1.2932x over previous
#include <cuda_runtime.h>
#include <cstdint>
#include <cstddef>

// ---------------------------------------------------------------------------
// BiLSTM T=1024 B=32 H=256 L=3, 3-gate cell, highway on l>0.
//   zx GEMMs: FFMA2 SGEMM BM128xBN128, 2-stage pipeline.
//   recurrence: 16 clusters x 8 CTAs (dir x 4-batch group). Wh in registers;
//   h pushed via DSMEM; FENCE-FREE sync: each pushing lane release-arrives
//   the rank it pushed to (count-32 mbarrier), so its own stores are ordered
//   by its own arrive. No fence.acq_rel.cluster, no pre-arrive syncthreads.
// ---------------------------------------------------------------------------

#define T_LEN 1024
#define BATCH 32
#define ZN    768
#define MROWS (T_LEN*BATCH)

__device__ float g_zxf[(size_t)MROWS * ZN];
__device__ float g_zxb[(size_t)MROWS * ZN];
__device__ float g_buf0[(size_t)MROWS * 512];
__device__ float g_buf1[(size_t)MROWS * 512];

__device__ __forceinline__ float sigm(float x) { return 1.f / (1.f + __expf(-x)); }

__device__ __forceinline__ unsigned long long pack2(float lo, float hi) {
    unsigned long long r;
    asm("mov.b64 %0, {%1, %2};" : "=l"(r) : "f"(lo), "f"(hi));
    return r;
}
__device__ __forceinline__ void unpack2(unsigned long long v, float& lo, float& hi) {
    asm("mov.b64 {%0, %1}, %2;" : "=f"(lo), "=f"(hi) : "l"(v));
}
__device__ __forceinline__ void ffma2(unsigned long long& d, unsigned long long a, unsigned long long b) {
    asm("fma.rn.f32x2 %0, %1, %2, %3;" : "=l"(d) : "l"(a), "l"(b), "l"(d));
}
__device__ __forceinline__ unsigned smaddr(const void* p) {
    unsigned a;
    asm("{ .reg .u64 t; cvta.to.shared.u64 t, %1; cvt.u32.u64 %0, t; }" : "=r"(a) : "l"(p));
    return a;
}
__device__ __forceinline__ unsigned mapa_addr(unsigned addr, unsigned rank) {
    unsigned ra;
    asm("mapa.shared::cluster.u32 %0, %1, %2;" : "=r"(ra) : "r"(addr), "r"(rank));
    return ra;
}
__device__ __forceinline__ void st_dsmem_f128(unsigned raddr, float4 v) {
    asm volatile("st.shared::cluster.v4.f32 [%0], {%1,%2,%3,%4};"
                 :: "r"(raddr), "f"(v.x), "f"(v.y), "f"(v.z), "f"(v.w) : "memory");
}
__device__ __forceinline__ void mbar_init(unsigned addr, unsigned cnt) {
    asm volatile("mbarrier.init.shared.b64 [%0], %1;" :: "r"(addr), "r"(cnt) : "memory");
}
__device__ __forceinline__ void mbar_arrive_dsmem(unsigned raddr) {
    asm volatile("mbarrier.arrive.shared::cluster.b64 _, [%0];" :: "r"(raddr) : "memory");
}
__device__ __forceinline__ void mbar_wait(unsigned addr, unsigned parity) {
    unsigned done;
    asm volatile("{ .reg .pred p; "
                 "mbarrier.try_wait.parity.acquire.cta.shared::cta.b64 p, [%1], %2; "
                 "selp.b32 %0, 1, 0, p; }"
                 : "=r"(done) : "r"(addr), "r"(parity) : "memory");
    if (!done) {
        asm volatile("{ .reg .pred P1; "
                     "WL_%=: mbarrier.try_wait.parity.acquire.cta.shared::cta.b64 P1, [%0], %1, 0x989680; "
                     "@P1 bra.uni WD_%=; bra.uni WL_%=; WD_%=: }"
                     :: "r"(addr), "r"(parity) : "memory");
    }
}
#define CLUSTER_SYNC() do { \
    asm volatile("barrier.cluster.arrive.aligned;" ::: "memory"); \
    asm volatile("barrier.cluster.wait.aligned;" ::: "memory"); \
} while (0)

// ------------------------- SGEMM (FFMA2, BM128 x BN128, 2-stage) -----------
#define BM 128
#define BN 128
#define BK 16

__global__ __launch_bounds__(256, 2) void sgemm_bias(
    const float* __restrict__ A, const float* __restrict__ B,
    const float* __restrict__ bias, float* __restrict__ C,
    int M, int N, int K)
{
    __shared__ float As[2][BK][BM];
    __shared__ float Bs[2][BK][BN];

    const int bm = blockIdx.y * BM;
    const int bn = blockIdx.x * BN;
    const int tid = threadIdx.x;
    const int tx = tid & 15;          // n-group: cols tx*4.. and 64+tx*4..
    const int ty = tid >> 4;          // m-group: rows ty*8..ty*8+8

    const int ar0 = tid >> 2;         // A rows ar0, 64+ar0
    const int ac4 = tid & 3;          // k-group
    const int brow = tid >> 4;        // B row
    const int bc = tid & 15;          // B col groups bc*4, 64+bc*4

    unsigned long long acc2[4][8];    // [m-pair][n]: n 0..3 -> colsA, 4..7 -> colsB
#pragma unroll
    for (int p = 0; p < 4; p++)
#pragma unroll
        for (int j = 0; j < 8; j++) acc2[p][j] = 0ull;

    const int nIter = K >> 4;

    float4 a0, a1, b0, b1;
    a0 = *(const float4*)(A + (size_t)(bm + ar0) * K + ac4 * 4);
    a1 = *(const float4*)(A + (size_t)(bm + 64 + ar0) * K + ac4 * 4);
    b0 = *(const float4*)(B + (size_t)brow * N + bn + bc * 4);
    b1 = *(const float4*)(B + (size_t)brow * N + bn + 64 + bc * 4);

    for (int it = 0; it < nIter; it++) {
        const int s = it & 1;
        As[s][ac4 * 4 + 0][ar0] = a0.x;
        As[s][ac4 * 4 + 1][ar0] = a0.y;
        As[s][ac4 * 4 + 2][ar0] = a0.z;
        As[s][ac4 * 4 + 3][ar0] = a0.w;
        As[s][ac4 * 4 + 0][64 + ar0] = a1.x;
        As[s][ac4 * 4 + 1][64 + ar0] = a1.y;
        As[s][ac4 * 4 + 2][64 + ar0] = a1.z;
        As[s][ac4 * 4 + 3][64 + ar0] = a1.w;
        *(float4*)&Bs[s][brow][bc * 4]      = b0;
        *(float4*)&Bs[s][brow][64 + bc * 4] = b1;
        __syncthreads();
        if (it + 1 < nIter) {
            int k0 = (it + 1) * BK;
            a0 = *(const float4*)(A + (size_t)(bm + ar0) * K + k0 + ac4 * 4);
            a1 = *(const float4*)(A + (size_t)(bm + 64 + ar0) * K + k0 + ac4 * 4);
            b0 = *(const float4*)(B + (size_t)(k0 + brow) * N + bn + bc * 4);
            b1 = *(const float4*)(B + (size_t)(k0 + brow) * N + bn + 64 + bc * 4);
        }
#pragma unroll
        for (int k = 0; k < BK; k++) {
            ulonglong2 A0 = *(const ulonglong2*)&As[s][k][ty * 8];
            ulonglong2 A1 = *(const ulonglong2*)&As[s][k][ty * 8 + 4];
            float4 bv0 = *(const float4*)&Bs[s][k][tx * 4];
            float4 bv1 = *(const float4*)&Bs[s][k][64 + tx * 4];
            unsigned long long bb;
#define NCOL(J, V)                                                     \
            bb = pack2(V, V);                                          \
            ffma2(acc2[0][J], A0.x, bb); ffma2(acc2[1][J], A0.y, bb);  \
            ffma2(acc2[2][J], A1.x, bb); ffma2(acc2[3][J], A1.y, bb);
            NCOL(0, bv0.x) NCOL(1, bv0.y) NCOL(2, bv0.z) NCOL(3, bv0.w)
            NCOL(4, bv1.x) NCOL(5, bv1.y) NCOL(6, bv1.z) NCOL(7, bv1.w)
#undef NCOL
        }
        __syncthreads();
    }
    float4 bbA = *(const float4*)(bias + bn + tx * 4);
    float4 bbB = *(const float4*)(bias + bn + 64 + tx * 4);
#pragma unroll
    for (int p = 0; p < 4; p++) {
        float lo[8], hi[8];
#pragma unroll
        for (int j = 0; j < 8; j++) unpack2(acc2[p][j], lo[j], hi[j]);
        int row0 = bm + ty * 8 + 2 * p;
        float4 o;
        o.x = lo[0] + bbA.x; o.y = lo[1] + bbA.y; o.z = lo[2] + bbA.z; o.w = lo[3] + bbA.w;
        *(float4*)(C + (size_t)row0 * N + bn + tx * 4) = o;
        o.x = lo[4] + bbB.x; o.y = lo[5] + bbB.y; o.z = lo[6] + bbB.z; o.w = lo[7] + bbB.w;
        *(float4*)(C + (size_t)row0 * N + bn + 64 + tx * 4) = o;
        o.x = hi[0] + bbA.x; o.y = hi[1] + bbA.y; o.z = hi[2] + bbA.z; o.w = hi[3] + bbA.w;
        *(float4*)(C + (size_t)(row0 + 1) * N + bn + tx * 4) = o;
        o.x = hi[4] + bbB.x; o.y = hi[5] + bbB.y; o.z = hi[6] + bbB.z; o.w = hi[7] + bbB.w;
        *(float4*)(C + (size_t)(row0 + 1) * N + bn + 64 + tx * 4) = o;
    }
}

// ------------------------- recurrent scan ----------------------------------
// 128 CTAs, cluster 8. cid = blockIdx.x/8; dir = cid>>3; bg = cid&7.
// CTA rank r owns h-cols [r*32, r*32+32) -> 96 z-cols x 4 batches. 384 thr.
// Dot: (jg = tid%24, kc = tid/24), W in regs (32 ull).
// Partials ZP[b][kc][j] (pitch 104/kc, 1672/b). Reduce on all 384 threads.
// Cell warps (0-3): cell math -> SH stage -> syncwarp -> lane r pushes the
// warp's 8 float4 to rank r and RELEASE-ARRIVES rank r's mbar (count 32).
// No fence / no trailing syncthreads. Arrives post-date bar2, which
// post-dates all dot reads -> 1-deep pipelining stays safe.
#define ZP_KP 104
#define ZP_BP 1672

__global__ void __cluster_dims__(8, 1, 1) __launch_bounds__(384, 1)
recur10(const float* __restrict__ Whf, const float* __restrict__ Whb,
        const float* __restrict__ h0, const float* __restrict__ c0,
        float* __restrict__ y, float* __restrict__ hn, float* __restrict__ cn,
        int layer)
{
    __shared__ __align__(16) float HS[2][4 * 264];   // h pingpong, [b][k] pitch 264
    __shared__ __align__(16) float ZP[4 * ZP_BP];    // dot partials
    __shared__ float ZF[96 * 4];                     // reduced gate sums
    __shared__ __align__(16) float SH[4 * 40];       // nh staging
    __shared__ unsigned long long hmb;               // mbarrier (count 32)

    const int cid = blockIdx.x >> 3;
    const int dir = cid >> 3;
    const int bg  = cid & 7;
    unsigned rank;
    asm("mov.u32 %0, %%cluster_ctarank;" : "=r"(rank));

    const float* Wh = dir ? Whb : Whf;
    const float* zx = dir ? g_zxb : g_zxf;
    const int tid = threadIdx.x;
    const unsigned hmb_a = smaddr(&hmb);

    const int jg = tid % 24;
    const int kc = tid / 24;
    const int rj = tid >> 2;
    const int rb = tid & 3;
    const int bglob_r = bg * 4 + rb;
    const int zcolr = (rj >> 5) * 256 + (int)rank * 32 + (rj & 31);

    // per-thread DSMEM delta for its push target (rank = lane&7)
    const unsigned anchor = smaddr(&HS[0][0]);
    const unsigned pdel = mapa_addr(anchor, (unsigned)(tid & 7)) - anchor;

    // ---- W slice into registers ----
    const int gate = jg >> 3;
    const int colb = (int)rank * 32 + (jg & 7) * 4;
    const int zc0 = gate * 256 + colb;
    unsigned long long wA[16], wB[16];
#pragma unroll
    for (int kl = 0; kl < 16; kl++) {
        const float* wrow = Wh + (size_t)(kc * 16 + kl) * ZN + zc0;
        wA[kl] = pack2(__ldg(wrow + 0), __ldg(wrow + 1));
        wB[kl] = pack2(__ldg(wrow + 2), __ldg(wrow + 3));
    }

    // ---- init h buffer 0, c, mbarrier ----
    for (int it = tid; it < 4 * 256; it += 384) {
        int b = it >> 8, k = it & 255;
        HS[0][b * 264 + k] = h0[k];
    }
    float creg = 0.f;
    if (tid < 128) creg = c0[(int)rank * 32 + (tid >> 2)];
    if (tid == 0) mbar_init(hmb_a, 32);
    __syncthreads();
    CLUSTER_SYNC();   // inits + HS[0] visible cluster-wide before any arrive

    const int t0 = dir ? (T_LEN - 1) : 0;
    float zxv = __ldg(&zx[((size_t)t0 * BATCH + bglob_r) * ZN + zcolr]);

    for (int tt = 0; tt < T_LEN; tt++) {
        const int t = dir ? (T_LEN - 1 - tt) : tt;

        if (tt) mbar_wait(hmb_a, (tt & 1) ^ 1);   // h[tt&1] ready

        // ---------------- dot (W in regs, h broadcast from SMEM) ----------
        const float* hc = &HS[tt & 1][kc * 16];
        unsigned long long acc[2][4];
#pragma unroll
        for (int g2 = 0; g2 < 2; g2++)
#pragma unroll
            for (int b = 0; b < 4; b++) acc[g2][b] = 0ull;

#pragma unroll
        for (int q = 0; q < 4; q++) {
            float4 h0q = *(const float4*)(hc + 0 * 264 + q * 4);
            float4 h1q = *(const float4*)(hc + 1 * 264 + q * 4);
            float4 h2q = *(const float4*)(hc + 2 * 264 + q * 4);
            float4 h3q = *(const float4*)(hc + 3 * 264 + q * 4);
#define RSTEP(C, KL)                                                   \
            {                                                          \
                unsigned long long p;                                  \
                p = pack2(h0q.C, h0q.C);                               \
                ffma2(acc[0][0], wA[KL], p); ffma2(acc[1][0], wB[KL], p); \
                p = pack2(h1q.C, h1q.C);                               \
                ffma2(acc[0][1], wA[KL], p); ffma2(acc[1][1], wB[KL], p); \
                p = pack2(h2q.C, h2q.C);                               \
                ffma2(acc[0][2], wA[KL], p); ffma2(acc[1][2], wB[KL], p); \
                p = pack2(h3q.C, h3q.C);                               \
                ffma2(acc[0][3], wA[KL], p); ffma2(acc[1][3], wB[KL], p); \
            }
            RSTEP(x, (q * 4 + 0)) RSTEP(y, (q * 4 + 1))
            RSTEP(z, (q * 4 + 2)) RSTEP(w, (q * 4 + 3))
#undef RSTEP
        }
#pragma unroll
        for (int b = 0; b < 4; b++) {
            ulonglong2 v;
            v.x = acc[0][b];
            v.y = acc[1][b];
            *(ulonglong2*)&ZP[b * ZP_BP + kc * ZP_KP + jg * 4] = v;
        }
        __syncthreads();   // bar 1: ZP ready

        // ---------------- reduce: all 384 threads, one (j,b) each ---------
        {
            float s = zxv;
            const float* zp = &ZP[rb * ZP_BP + rj];
#pragma unroll
            for (int k2 = 0; k2 < 16; k2++) s += zp[k2 * ZP_KP];
            ZF[rj * 4 + rb] = s;
        }
        if (tt + 1 < T_LEN) {
            const int tn = dir ? (t - 1) : (t + 1);
            zxv = __ldg(&zx[((size_t)tn * BATCH + bglob_r) * ZN + zcolr]);
        }
        __syncthreads();   // bar 2: ZF ready (post-dates ALL dot reads)

        // ---------------- cell + push + distributed release-arrive --------
        if (tid < 128) {
            const int m = tid >> 2;
            const int b = tid & 3;
            const int w = tid >> 5;
            const int lane = tid & 31;
            float iv = ZF[m * 4 + b];
            float jv = ZF[(32 + m) * 4 + b];
            float ov = ZF[(64 + m) * 4 + b];
            float ig = sigm(iv);
            creg = (1.f - ig) * creg + ig * tanhf(jv);
            float nh = tanhf(creg) * sigm(ov);

            SH[b * 40 + m] = nh;
            __syncwarp();
            if ((tt + 1 < T_LEN) && lane < 8) {
                // lane pushes this warp's 8 cols x 4 batches to rank==lane,
                // then release-arrives that rank's mbar (orders OWN stores).
                const unsigned hb = smaddr(&HS[(tt + 1) & 1][0]) + pdel;
#pragma unroll
                for (int pb = 0; pb < 4; pb++) {
#pragma unroll
                    for (int half = 0; half < 2; half++) {
                        const int base = w * 8 + half * 4;
                        float4 v = *(const float4*)&SH[pb * 40 + base];
                        st_dsmem_f128(hb + (pb * 264 + (int)rank * 32 + base) * 4, v);
                    }
                }
                mbar_arrive_dsmem(hmb_a + pdel);
            }

            const int col = (int)rank * 32 + m;
            const int bglob = bg * 4 + b;
            y[((size_t)t * BATCH + bglob) * 512 + dir * 256 + col] = nh;
            if (tt == T_LEN - 1) {
                int si = 2 * layer + dir;
                hn[(size_t)si * (BATCH * 256) + bglob * 256 + col] = nh;
                cn[(size_t)si * (BATCH * 256) + bglob * 256 + col] = creg;
            }
        }
        // non-cell warps proceed straight to next step's wait
    }
}

// ------------------------- highway elementwise -----------------------------
__global__ __launch_bounds__(256) void highway_ew(
    const float4* __restrict__ gz, const float4* __restrict__ raw,
    const float4* __restrict__ prev, float4* __restrict__ dst, int n4)
{
    int i = blockIdx.x * blockDim.x + threadIdx.x;
    if (i < n4) {
        float4 G = gz[i], R = raw[i], P = prev[i], o;
        float s;
        s = sigm(G.x); o.x = s * R.x + (1.f - s) * P.x;
        s = sigm(G.y); o.y = s * R.y + (1.f - s) * P.y;
        s = sigm(G.z); o.z = s * R.z + (1.f - s) * P.z;
        s = sigm(G.w); o.w = s * R.w + (1.f - s) * P.w;
        dst[i] = o;
    }
}

// ------------------------- host launcher -----------------------------------
extern "C" void kernel_launch(void* const* d_in, const int* in_sizes, int n_in,
                              void* d_out, int out_size)
{
    (void)in_sizes; (void)n_in; (void)out_size;

    const float* x    = (const float*)d_in[0];
    const float* h0   = (const float*)d_in[1];
    const float* c0   = (const float*)d_in[2];
    const float* Wf0  = (const float*)d_in[3];
    const float* bf0  = (const float*)d_in[4];
    const float* Wb0  = (const float*)d_in[5];
    const float* bb0  = (const float*)d_in[6];
    const float* Wf1  = (const float*)d_in[7];
    const float* bf1  = (const float*)d_in[8];
    const float* Wb1  = (const float*)d_in[9];
    const float* bb1  = (const float*)d_in[10];
    const float* Wf2  = (const float*)d_in[11];
    const float* bf2  = (const float*)d_in[12];
    const float* Wb2  = (const float*)d_in[13];
    const float* bb2  = (const float*)d_in[14];
    const float* W_hw = (const float*)d_in[15];
    const float* b_hw = (const float*)d_in[16];

    float* out = (float*)d_out;
    float* hn  = out + (size_t)MROWS * 512;
    float* cn  = hn + 6 * BATCH * 256;

    float *zxf, *zxb, *buf0, *buf1;
    cudaGetSymbolAddress((void**)&zxf,  g_zxf);
    cudaGetSymbolAddress((void**)&zxb,  g_zxb);
    cudaGetSymbolAddress((void**)&buf0, g_buf0);
    cudaGetSymbolAddress((void**)&buf1, g_buf1);

    const dim3 g768(ZN / BN, MROWS / BM);   // (6, 256)
    const dim3 g512(512 / BN, MROWS / BM);  // (4, 256)
    const int n4 = (MROWS * 512) / 4;
    const int ewb = (n4 + 255) / 256;

    // ---- layer 0 ----
    sgemm_bias<<<g768, 256>>>(x, Wf0, bf0, zxf, MROWS, ZN, 256);
    sgemm_bias<<<g768, 256>>>(x, Wb0, bb0, zxb, MROWS, ZN, 256);
    recur10<<<128, 384>>>(Wf0 + (size_t)256 * ZN, Wb0 + (size_t)256 * ZN,
                          h0, c0, buf0, hn, cn, 0);
    // ---- layer 1 ----
    sgemm_bias<<<g768, 256>>>(buf0, Wf1, bf1, zxf, MROWS, ZN, 512);
    sgemm_bias<<<g768, 256>>>(buf0, Wb1, bb1, zxb, MROWS, ZN, 512);
    recur10<<<128, 384>>>(Wf1 + (size_t)512 * ZN, Wb1 + (size_t)512 * ZN,
                          h0, c0, buf1, hn, cn, 1);
    sgemm_bias<<<g512, 256>>>(buf1, W_hw, b_hw, zxf, MROWS, 512, 512);
    highway_ew<<<ewb, 256>>>((const float4*)zxf, (const float4*)buf1,
                             (const float4*)buf0, (float4*)buf1, n4);
    // ---- layer 2 ----
    sgemm_bias<<<g768, 256>>>(buf1, Wf2, bf2, zxf, MROWS, ZN, 512);
    sgemm_bias<<<g768, 256>>>(buf1, Wb2, bb2, zxb, MROWS, ZN, 512);
    recur10<<<128, 384>>>(Wf2 + (size_t)512 * ZN, Wb2 + (size_t)512 * ZN,
                          h0, c0, buf0, hn, cn, 2);
    sgemm_bias<<<g512, 256>>>(buf0, W_hw, b_hw, zxf, MROWS, 512, 512);
    highway_ew<<<ewb, 256>>>((const float4*)zxf, (const float4*)buf0,
                             (const float4*)buf1, (float4*)out, n4);
}